// round 3
// baseline (speedup 1.0000x reference)
#include <cuda_runtime.h>
#include <math.h>

// Problem constants
constexpr int S   = 1024;   // tokens
constexpr int H   = 2048;   // hidden
constexpr int NH  = 16;     // q heads
constexpr int NKV = 4;      // kv heads
constexpr int D   = 128;    // head dim
constexpr int E   = 64;     // experts
constexpr int TK  = 8;      // top_k
constexpr int IM  = 768;    // moe intermediate
constexpr float EPS = 1e-6f;
constexpr int NA = S * TK;  // total assignments = 8192

// ---------------- scratch (device globals; no allocation allowed) ----------
__device__ float g_xnorm [S * H];
__device__ float g_q     [S * NH * D];
__device__ float g_k     [S * NKV * D];
__device__ float g_v     [S * NKV * D];
__device__ float g_ctx   [S * NH * D];
__device__ float g_hid2  [S * H];
__device__ float g_hnorm [S * H];
__device__ int   g_topk_id[NA];
__device__ float g_topk_w [NA];
__device__ int   g_cnt   [E];
__device__ int   g_off   [E + 1];
__device__ int   g_cur   [E];
__device__ int   g_tok   [NA];     // expert-grouped token index
__device__ float g_ew    [NA];     // expert-grouped combine weight
__device__ int   g_dst   [NA];     // expert-grouped dest row (= t*8+k)
__device__ float g_act   [NA * IM];        // weighted SwiGLU activations
__device__ float g_part  [(size_t)NA * H]; // per-assignment down-proj rows

// Buffer-id -> device global pointer (valid only in device code)
__device__ __forceinline__ float* bufptr(int b) {
    switch (b) {
        case 0: return g_xnorm;
        case 1: return g_q;
        case 2: return g_k;
        case 3: return g_v;
        case 4: return g_ctx;
        case 5: return g_hid2;
        case 6: return g_hnorm;
    }
    return nullptr;
}

// ---------------- RMSNorm ----------------
// x source: external pointer if x_ext != nullptr, else buffer id xBuf.
__global__ void rmsnorm_k(const float* __restrict__ x_ext, int xBuf,
                          const float* __restrict__ g, int outBuf) {
    const float* x = x_ext ? x_ext : bufptr(xBuf);
    float* out = bufptr(outBuf);
    int row = blockIdx.x, tid = threadIdx.x;
    const float* xr = x + (size_t)row * H;
    float ss = 0.f;
    for (int j = tid; j < H; j += 256) { float v = xr[j]; ss += v * v; }
    for (int o = 16; o; o >>= 1) ss += __shfl_xor_sync(0xffffffffu, ss, o);
    __shared__ float red[8];
    if ((tid & 31) == 0) red[tid >> 5] = ss;
    __syncthreads();
    if (tid < 32) {
        float v = (tid < 8) ? red[tid] : 0.f;
        for (int o = 4; o; o >>= 1) v += __shfl_xor_sync(0xffffffffu, v, o);
        if (tid == 0) red[0] = v;
    }
    __syncthreads();
    float inv = rsqrtf(red[0] / (float)H + EPS);
    for (int j = tid; j < H; j += 256) out[(size_t)row * H + j] = xr[j] * inv * g[j];
}

// ---------------- generic tiled SGEMM: C = (res?) + A[M,K] @ B[K,N] --------
// A and C are scratch buffers (by id); B and res are external pointers.
__global__ __launch_bounds__(256) void sgemm64(int aBuf,
                                               const float* __restrict__ B,
                                               const float* __restrict__ res,
                                               int cBuf,
                                               int M, int N, int K) {
    const float* A = bufptr(aBuf);
    float* C = bufptr(cBuf);
    __shared__ float As[16][65];
    __shared__ float Bs[16][64];
    int n0 = blockIdx.x * 64, m0 = blockIdx.y * 64;
    int tid = threadIdx.x;
    int tx = tid & 15, ty = tid >> 4;
    int aRow = tid >> 2, aCol = (tid & 3) * 4;
    int bRow = tid >> 4, bCol = (tid & 15) * 4;
    float acc[4][4] = {};
    for (int k0 = 0; k0 < K; k0 += 16) {
        #pragma unroll
        for (int j = 0; j < 4; j++)
            As[aCol + j][aRow] = A[(size_t)(m0 + aRow) * K + k0 + aCol + j];
        #pragma unroll
        for (int j = 0; j < 4; j++)
            Bs[bRow][bCol + j] = B[(size_t)(k0 + bRow) * N + n0 + bCol + j];
        __syncthreads();
        #pragma unroll
        for (int kk = 0; kk < 16; kk++) {
            float ra[4], rb[4];
            #pragma unroll
            for (int i = 0; i < 4; i++) ra[i] = As[kk][ty * 4 + i];
            #pragma unroll
            for (int j = 0; j < 4; j++) rb[j] = Bs[kk][tx * 4 + j];
            #pragma unroll
            for (int i = 0; i < 4; i++)
                #pragma unroll
                for (int j = 0; j < 4; j++) acc[i][j] += ra[i] * rb[j];
        }
        __syncthreads();
    }
    #pragma unroll
    for (int i = 0; i < 4; i++)
        #pragma unroll
        for (int j = 0; j < 4; j++) {
            size_t idx = (size_t)(m0 + ty * 4 + i) * N + n0 + tx * 4 + j;
            float v = acc[i][j];
            if (res) v += res[idx];
            C[idx] = v;
        }
}

// ---------------- causal flash attention (fp32) ----------------
// grid (S/64, NH), block 256. 4 threads per query (32 dims each), 32-key tiles.
__global__ __launch_bounds__(256) void attn_k() {
    constexpr int QT = 64, KT = 32;
    constexpr float SC = 0.0883883476483184f; // 1/sqrt(128)
    int qt = blockIdx.x, h = blockIdx.y;
    int kvh = h / (NH / NKV);
    int tid = threadIdx.x;
    int qi = tid >> 2, qr = tid & 3;
    int qrow = qt * QT + qi;
    int d0 = qr * 32;
    __shared__ float Ks[KT][D];
    __shared__ float Vs[KT][D];
    float qreg[32], acc[32];
    #pragma unroll
    for (int d = 0; d < 32; d++) {
        qreg[d] = g_q[(size_t)qrow * (NH * D) + h * D + d0 + d] * SC;
        acc[d] = 0.f;
    }
    float m = -1e30f, l = 0.f;
    int ktiles = qt * 2 + 2;  // keys up to qt*64+63
    for (int kt = 0; kt < ktiles; kt++) {
        int kb = kt * KT;
        for (int idx = tid; idx < KT * D; idx += 256) {
            int r = idx >> 7, c = idx & 127;
            Ks[r][c] = g_k[(size_t)(kb + r) * (NKV * D) + kvh * D + c];
            Vs[r][c] = g_v[(size_t)(kb + r) * (NKV * D) + kvh * D + c];
        }
        __syncthreads();
        float sc[KT];
        #pragma unroll
        for (int j = 0; j < KT; j++) {
            float p = 0.f;
            #pragma unroll
            for (int d = 0; d < 32; d++) p += qreg[d] * Ks[j][d0 + d];
            p += __shfl_xor_sync(0xffffffffu, p, 1);
            p += __shfl_xor_sync(0xffffffffu, p, 2);
            sc[j] = (kb + j <= qrow) ? p : -1e30f;
        }
        float tm = m;
        #pragma unroll
        for (int j = 0; j < KT; j++) tm = fmaxf(tm, sc[j]);
        float corr = __expf(m - tm);
        m = tm;
        l *= corr;
        #pragma unroll
        for (int d = 0; d < 32; d++) acc[d] *= corr;
        #pragma unroll
        for (int j = 0; j < KT; j++) {
            float p = __expf(sc[j] - m);
            l += p;
            #pragma unroll
            for (int d = 0; d < 32; d++) acc[d] += p * Vs[j][d0 + d];
        }
        __syncthreads();
    }
    float inv = 1.f / l;
    #pragma unroll
    for (int d = 0; d < 32; d++)
        g_ctx[(size_t)qrow * (NH * D) + h * D + d0 + d] = acc[d] * inv;
}

// ---------------- router: logits, softmax-top8, counts ----------------
__global__ void zero_cnt_k() { if (threadIdx.x < E) g_cnt[threadIdx.x] = 0; }

__global__ void router_k(const float* __restrict__ Wg) {
    int t = blockIdx.x, tid = threadIdx.x;   // blockDim = 64
    __shared__ float sh[H];
    __shared__ float lg[E];
    for (int j = tid; j < H; j += 64) sh[j] = g_hnorm[(size_t)t * H + j];
    __syncthreads();
    float lo = 0.f;
    for (int j = 0; j < H; j++) lo += sh[j] * Wg[(size_t)j * E + tid];
    lg[tid] = lo;
    __syncthreads();
    if (tid == 0) {
        float tmp[E];
        for (int e = 0; e < E; e++) tmp[e] = lg[e];
        int   id[TK]; float w[TK];
        for (int k = 0; k < TK; k++) {
            int best = 0; float bv = tmp[0];
            for (int e = 1; e < E; e++) if (tmp[e] > bv) { bv = tmp[e]; best = e; }
            id[k] = best; w[k] = bv; tmp[best] = -1e30f;
        }
        float mx = w[0], s = 0.f;
        for (int k = 0; k < TK; k++) { w[k] = expf(w[k] - mx); s += w[k]; }
        float inv = 1.f / s;
        for (int k = 0; k < TK; k++) {
            g_topk_id[t * TK + k] = id[k];
            g_topk_w [t * TK + k] = w[k] * inv;
            atomicAdd(&g_cnt[id[k]], 1);
        }
    }
}

__global__ void offsets_k() {
    if (threadIdx.x == 0) {
        int run = 0;
        for (int e = 0; e < E; e++) { g_off[e] = run; g_cur[e] = run; run += g_cnt[e]; }
        g_off[E] = run;
    }
}

__global__ void scatter_k() {
    int a = blockIdx.x * blockDim.x + threadIdx.x;
    if (a < NA) {
        int e = g_topk_id[a];
        int pos = atomicAdd(&g_cur[e], 1);
        g_tok[pos] = a >> 3;
        g_ew [pos] = g_topk_w[a];
        g_dst[pos] = a;
    }
}

// ---------------- MoE gate/up GEMM + SwiGLU + weight ----------------
// grid (IM/64, 32, E), block 256. BM=32 tokens, BN=64, BK=32.
__global__ __launch_bounds__(256) void moe_act_k(const float* __restrict__ Wgate,
                                                 const float* __restrict__ Wup) {
    int e = blockIdx.z;
    int base = g_off[e], cnt = g_off[e + 1] - base;
    int t0 = blockIdx.y * 32;
    if (t0 >= cnt) return;
    int i0 = blockIdx.x * 64;
    __shared__ float Hs[32][33];
    __shared__ float Wgs[32][64];
    __shared__ float Wus[32][64];
    __shared__ int   stok[32];
    __shared__ float sw[32];
    __shared__ int   sdst[32];
    int tid = threadIdx.x;
    if (tid < 32) {
        int r = t0 + tid;
        if (r < cnt) { stok[tid] = g_tok[base + r]; sw[tid] = g_ew[base + r]; sdst[tid] = g_dst[base + r]; }
        else         { stok[tid] = 0; sw[tid] = 0.f; sdst[tid] = -1; }
    }
    __syncthreads();
    const float* WgE = Wgate + (size_t)e * H * IM;
    const float* WuE = Wup   + (size_t)e * H * IM;
    int tx = tid & 15, ty = tid >> 4;
    float ag[2][4] = {}, au[2][4] = {};
    for (int k0 = 0; k0 < H; k0 += 32) {
        #pragma unroll
        for (int u = 0; u < 4; u++) {
            int idx = tid + u * 256; int r = idx >> 5, c = idx & 31;
            Hs[r][c] = g_hnorm[(size_t)stok[r] * H + k0 + c];
        }
        #pragma unroll
        for (int u = 0; u < 8; u++) {
            int idx = tid + u * 256; int r = idx >> 6, c = idx & 63;
            Wgs[r][c] = WgE[(size_t)(k0 + r) * IM + i0 + c];
            Wus[r][c] = WuE[(size_t)(k0 + r) * IM + i0 + c];
        }
        __syncthreads();
        #pragma unroll
        for (int kk = 0; kk < 32; kk++) {
            float h0 = Hs[ty * 2][kk], h1 = Hs[ty * 2 + 1][kk];
            #pragma unroll
            for (int j = 0; j < 4; j++) {
                float wg = Wgs[kk][tx * 4 + j], wu = Wus[kk][tx * 4 + j];
                ag[0][j] += h0 * wg; ag[1][j] += h1 * wg;
                au[0][j] += h0 * wu; au[1][j] += h1 * wu;
            }
        }
        __syncthreads();
    }
    #pragma unroll
    for (int r = 0; r < 2; r++) {
        int rr = ty * 2 + r;
        if (t0 + rr < cnt) {
            int dd = sdst[rr]; float w = sw[rr];
            #pragma unroll
            for (int j = 0; j < 4; j++) {
                float gg = ag[r][j], uu = au[r][j];
                float a = (gg / (1.f + __expf(-gg))) * uu * w;   // silu(g)*u*combine
                g_act[(size_t)dd * IM + i0 + tx * 4 + j] = a;
            }
        }
    }
}

// ---------------- MoE down GEMM -> per-assignment partial rows -------------
// grid (H/64, 32, E), block 256. BM=32, BN=64, BK=32, K=IM=768.
__global__ __launch_bounds__(256) void moe_down_k(const float* __restrict__ Wdown) {
    int e = blockIdx.z;
    int base = g_off[e], cnt = g_off[e + 1] - base;
    int t0 = blockIdx.y * 32;
    if (t0 >= cnt) return;
    int h0 = blockIdx.x * 64;
    __shared__ float As2[32][33];
    __shared__ float Bs2[32][64];
    __shared__ int   sdst[32];
    int tid = threadIdx.x;
    if (tid < 32) {
        int r = t0 + tid;
        sdst[tid] = (r < cnt) ? g_dst[base + r] : -1;
    }
    __syncthreads();
    const float* WdE = Wdown + (size_t)e * IM * H;
    int tx = tid & 15, ty = tid >> 4;
    float acc[2][4] = {};
    for (int k0 = 0; k0 < IM; k0 += 32) {
        #pragma unroll
        for (int u = 0; u < 4; u++) {
            int idx = tid + u * 256; int r = idx >> 5, c = idx & 31;
            As2[r][c] = (sdst[r] >= 0) ? g_act[(size_t)sdst[r] * IM + k0 + c] : 0.f;
        }
        #pragma unroll
        for (int u = 0; u < 8; u++) {
            int idx = tid + u * 256; int r = idx >> 6, c = idx & 63;
            Bs2[r][c] = WdE[(size_t)(k0 + r) * H + h0 + c];
        }
        __syncthreads();
        #pragma unroll
        for (int kk = 0; kk < 32; kk++) {
            float a0 = As2[ty * 2][kk], a1 = As2[ty * 2 + 1][kk];
            #pragma unroll
            for (int j = 0; j < 4; j++) {
                float b = Bs2[kk][tx * 4 + j];
                acc[0][j] += a0 * b; acc[1][j] += a1 * b;
            }
        }
        __syncthreads();
    }
    #pragma unroll
    for (int r = 0; r < 2; r++) {
        int rr = ty * 2 + r;
        if (t0 + rr < cnt) {
            int dd = sdst[rr];
            #pragma unroll
            for (int j = 0; j < 4; j++)
                g_part[(size_t)dd * H + h0 + tx * 4 + j] = acc[r][j];
        }
    }
}

// ---------------- finalize: residual + sum of 8 partial rows ---------------
__global__ void finalize_k(float* __restrict__ out) {
    size_t idx = (size_t)blockIdx.x * 256 + threadIdx.x;   // S*H total
    int t = (int)(idx >> 11);
    int hc = (int)(idx & 2047);
    float v = g_hid2[idx];
    #pragma unroll
    for (int k = 0; k < TK; k++)
        v += g_part[(size_t)(t * TK + k) * H + hc];
    out[idx] = v;
}

// ---------------- launch ----------------
extern "C" void kernel_launch(void* const* d_in, const int* in_sizes, int n_in,
                              void* d_out, int out_size) {
    const float* hidden = (const float*)d_in[0];
    const float* ln1_g  = (const float*)d_in[1];
    const float* ln2_g  = (const float*)d_in[2];
    const float* Wq     = (const float*)d_in[3];
    const float* Wk     = (const float*)d_in[4];
    const float* Wv     = (const float*)d_in[5];
    const float* Wo     = (const float*)d_in[6];
    const float* Wg     = (const float*)d_in[7];
    const float* Wgate  = (const float*)d_in[8];
    const float* Wup    = (const float*)d_in[9];
    const float* Wdown  = (const float*)d_in[10];
    float* out = (float*)d_out;

    // 1. input RMSNorm -> buf0 (xnorm)
    rmsnorm_k<<<S, 256>>>(hidden, -1, ln1_g, 0);
    // 2. QKV projections: A=xnorm(0) -> q(1), k(2), v(3)
    sgemm64<<<dim3((NH * D) / 64, S / 64), 256>>>(0, Wq, nullptr, 1, S, NH * D, H);
    sgemm64<<<dim3((NKV * D) / 64, S / 64), 256>>>(0, Wk, nullptr, 2, S, NKV * D, H);
    sgemm64<<<dim3((NKV * D) / 64, S / 64), 256>>>(0, Wv, nullptr, 3, S, NKV * D, H);
    // 3. causal GQA attention -> ctx(4)
    attn_k<<<dim3(S / 64, NH), 256>>>();
    // 4. output projection + residual: A=ctx(4), res=hidden -> hid2(5)
    sgemm64<<<dim3(H / 64, S / 64), 256>>>(4, Wo, hidden, 5, S, H, NH * D);
    // 5. post-attn RMSNorm: hid2(5) -> hnorm(6)
    rmsnorm_k<<<S, 256>>>(nullptr, 5, ln2_g, 6);
    // 6. router + dispatch
    zero_cnt_k<<<1, 64>>>();
    router_k<<<S, 64>>>(Wg);
    offsets_k<<<1, 1>>>();
    scatter_k<<<(NA + 255) / 256, 256>>>();
    // 7. expert gate/up + SwiGLU (sparse: only routed tokens)
    moe_act_k<<<dim3(IM / 64, 32, E), 256>>>(Wgate, Wup);
    // 8. expert down-proj into per-assignment rows
    moe_down_k<<<dim3(H / 64, 32, E), 256>>>(Wdown);
    // 9. residual + combine
    finalize_k<<<(S * H) / 256, 256>>>(out);
    (void)in_sizes; (void)n_in; (void)out_size;
}

// round 4
// speedup vs baseline: 1.1011x; 1.1011x over previous
#include <cuda_runtime.h>
#include <math.h>

// Problem constants
constexpr int S   = 1024;   // tokens
constexpr int H   = 2048;   // hidden
constexpr int NH  = 16;     // q heads
constexpr int NKV = 4;      // kv heads
constexpr int D   = 128;    // head dim
constexpr int E   = 64;     // experts
constexpr int TK  = 8;      // top_k
constexpr int IM  = 768;    // moe intermediate
constexpr float EPS = 1e-6f;
constexpr int NA = S * TK;  // total assignments = 8192
constexpr int KC = 16;      // MoE MMA K-chunk

// ---------------- scratch (device globals; no allocation allowed) ----------
__device__ float g_xnorm [S * H];
__device__ float g_q     [S * NH * D];
__device__ float g_k     [S * NKV * D];
__device__ float g_v     [S * NKV * D];
__device__ float g_ctx   [S * NH * D];
__device__ float g_hid2  [S * H];
__device__ float g_hnorm [S * H];
__device__ int   g_topk_id[NA];
__device__ float g_topk_w [NA];
__device__ int   g_cnt   [E];
__device__ int   g_off   [E + 1];
__device__ int   g_cur   [E];
__device__ int   g_tok   [NA];     // expert-grouped token index
__device__ float g_ew    [NA];     // expert-grouped combine weight
__device__ int   g_pos   [NA];     // assignment a -> expert-grouped row
__device__ float g_act   [NA * IM];        // grouped weighted SwiGLU activations
__device__ float g_part  [(size_t)NA * H]; // grouped down-proj rows

// Buffer-id -> device global pointer (valid only in device code)
__device__ __forceinline__ float* bufptr(int b) {
    switch (b) {
        case 0: return g_xnorm;
        case 1: return g_q;
        case 2: return g_k;
        case 3: return g_v;
        case 4: return g_ctx;
        case 5: return g_hid2;
        case 6: return g_hnorm;
    }
    return nullptr;
}

// ---------------- tf32 helpers ----------------
__device__ __forceinline__ unsigned f2tf(float f) {
    unsigned u; asm("cvt.rna.tf32.f32 %0, %1;" : "=r"(u) : "f"(f)); return u;
}
__device__ __forceinline__ void split_tf(float v, float& hi, float& lo) {
    hi = __uint_as_float(f2tf(v));
    lo = __uint_as_float(f2tf(v - hi));
}
__device__ __forceinline__ void mma_tf32(float c[4], const unsigned a[4], const unsigned b[2]) {
    asm volatile(
        "mma.sync.aligned.m16n8k8.row.col.f32.tf32.tf32.f32 "
        "{%0,%1,%2,%3}, {%4,%5,%6,%7}, {%8,%9}, {%0,%1,%2,%3};\n"
        : "+f"(c[0]), "+f"(c[1]), "+f"(c[2]), "+f"(c[3])
        : "r"(a[0]), "r"(a[1]), "r"(a[2]), "r"(a[3]), "r"(b[0]), "r"(b[1]));
}

// ---------------- RMSNorm ----------------
__global__ void rmsnorm_k(const float* __restrict__ x_ext, int xBuf,
                          const float* __restrict__ g, int outBuf) {
    const float* x = x_ext ? x_ext : bufptr(xBuf);
    float* out = bufptr(outBuf);
    int row = blockIdx.x, tid = threadIdx.x;
    const float* xr = x + (size_t)row * H;
    float ss = 0.f;
    for (int j = tid; j < H; j += 256) { float v = xr[j]; ss += v * v; }
    for (int o = 16; o; o >>= 1) ss += __shfl_xor_sync(0xffffffffu, ss, o);
    __shared__ float red[8];
    if ((tid & 31) == 0) red[tid >> 5] = ss;
    __syncthreads();
    if (tid < 32) {
        float v = (tid < 8) ? red[tid] : 0.f;
        for (int o = 4; o; o >>= 1) v += __shfl_xor_sync(0xffffffffu, v, o);
        if (tid == 0) red[0] = v;
    }
    __syncthreads();
    float inv = rsqrtf(red[0] / (float)H + EPS);
    for (int j = tid; j < H; j += 256) out[(size_t)row * H + j] = xr[j] * inv * g[j];
}

// ---------------- generic tiled SGEMM: C = (res?) + A[M,K] @ B[K,N] --------
__global__ __launch_bounds__(256) void sgemm64(int aBuf,
                                               const float* __restrict__ B,
                                               const float* __restrict__ res,
                                               int cBuf,
                                               int M, int N, int K) {
    const float* A = bufptr(aBuf);
    float* C = bufptr(cBuf);
    __shared__ float As[16][65];
    __shared__ float Bs[16][64];
    int n0 = blockIdx.x * 64, m0 = blockIdx.y * 64;
    int tid = threadIdx.x;
    int tx = tid & 15, ty = tid >> 4;
    int aRow = tid >> 2, aCol = (tid & 3) * 4;
    int bRow = tid >> 4, bCol = (tid & 15) * 4;
    float acc[4][4] = {};
    for (int k0 = 0; k0 < K; k0 += 16) {
        #pragma unroll
        for (int j = 0; j < 4; j++)
            As[aCol + j][aRow] = A[(size_t)(m0 + aRow) * K + k0 + aCol + j];
        #pragma unroll
        for (int j = 0; j < 4; j++)
            Bs[bRow][bCol + j] = B[(size_t)(k0 + bRow) * N + n0 + bCol + j];
        __syncthreads();
        #pragma unroll
        for (int kk = 0; kk < 16; kk++) {
            float ra[4], rb[4];
            #pragma unroll
            for (int i = 0; i < 4; i++) ra[i] = As[kk][ty * 4 + i];
            #pragma unroll
            for (int j = 0; j < 4; j++) rb[j] = Bs[kk][tx * 4 + j];
            #pragma unroll
            for (int i = 0; i < 4; i++)
                #pragma unroll
                for (int j = 0; j < 4; j++) acc[i][j] += ra[i] * rb[j];
        }
        __syncthreads();
    }
    #pragma unroll
    for (int i = 0; i < 4; i++)
        #pragma unroll
        for (int j = 0; j < 4; j++) {
            size_t idx = (size_t)(m0 + ty * 4 + i) * N + n0 + tx * 4 + j;
            float v = acc[i][j];
            if (res) v += res[idx];
            C[idx] = v;
        }
}

// ---------------- causal flash attention (fp32) ----------------
__global__ __launch_bounds__(256) void attn_k() {
    constexpr int QT = 64, KT = 32;
    constexpr float SC = 0.0883883476483184f; // 1/sqrt(128)
    int qt = blockIdx.x, h = blockIdx.y;
    int kvh = h / (NH / NKV);
    int tid = threadIdx.x;
    int qi = tid >> 2, qr = tid & 3;
    int qrow = qt * QT + qi;
    int d0 = qr * 32;
    __shared__ float Ks[KT][D];
    __shared__ float Vs[KT][D];
    float qreg[32], acc[32];
    #pragma unroll
    for (int d = 0; d < 32; d++) {
        qreg[d] = g_q[(size_t)qrow * (NH * D) + h * D + d0 + d] * SC;
        acc[d] = 0.f;
    }
    float m = -1e30f, l = 0.f;
    int ktiles = qt * 2 + 2;
    for (int kt = 0; kt < ktiles; kt++) {
        int kb = kt * KT;
        for (int idx = tid; idx < KT * D; idx += 256) {
            int r = idx >> 7, c = idx & 127;
            Ks[r][c] = g_k[(size_t)(kb + r) * (NKV * D) + kvh * D + c];
            Vs[r][c] = g_v[(size_t)(kb + r) * (NKV * D) + kvh * D + c];
        }
        __syncthreads();
        float sc[KT];
        #pragma unroll
        for (int j = 0; j < KT; j++) {
            float p = 0.f;
            #pragma unroll
            for (int d = 0; d < 32; d++) p += qreg[d] * Ks[j][d0 + d];
            p += __shfl_xor_sync(0xffffffffu, p, 1);
            p += __shfl_xor_sync(0xffffffffu, p, 2);
            sc[j] = (kb + j <= qrow) ? p : -1e30f;
        }
        float tm = m;
        #pragma unroll
        for (int j = 0; j < KT; j++) tm = fmaxf(tm, sc[j]);
        float corr = __expf(m - tm);
        m = tm;
        l *= corr;
        #pragma unroll
        for (int d = 0; d < 32; d++) acc[d] *= corr;
        #pragma unroll
        for (int j = 0; j < KT; j++) {
            float p = __expf(sc[j] - m);
            l += p;
            #pragma unroll
            for (int d = 0; d < 32; d++) acc[d] += p * Vs[j][d0 + d];
        }
        __syncthreads();
    }
    float inv = 1.f / l;
    #pragma unroll
    for (int d = 0; d < 32; d++)
        g_ctx[(size_t)qrow * (NH * D) + h * D + d0 + d] = acc[d] * inv;
}

// ---------------- router: logits, softmax-top8, counts ----------------
__global__ void zero_cnt_k() { if (threadIdx.x < E) g_cnt[threadIdx.x] = 0; }

__global__ void router_k(const float* __restrict__ Wg) {
    int t = blockIdx.x, tid = threadIdx.x;   // blockDim = 64
    __shared__ float sh[H];
    __shared__ float lg[E];
    for (int j = tid; j < H; j += 64) sh[j] = g_hnorm[(size_t)t * H + j];
    __syncthreads();
    float lo = 0.f;
    for (int j = 0; j < H; j++) lo += sh[j] * Wg[(size_t)j * E + tid];
    lg[tid] = lo;
    __syncthreads();
    if (tid == 0) {
        float tmp[E];
        for (int e = 0; e < E; e++) tmp[e] = lg[e];
        int   id[TK]; float w[TK];
        for (int k = 0; k < TK; k++) {
            int best = 0; float bv = tmp[0];
            for (int e = 1; e < E; e++) if (tmp[e] > bv) { bv = tmp[e]; best = e; }
            id[k] = best; w[k] = bv; tmp[best] = -1e30f;
        }
        float mx = w[0], s = 0.f;
        for (int k = 0; k < TK; k++) { w[k] = expf(w[k] - mx); s += w[k]; }
        float inv = 1.f / s;
        for (int k = 0; k < TK; k++) {
            g_topk_id[t * TK + k] = id[k];
            g_topk_w [t * TK + k] = w[k] * inv;
            atomicAdd(&g_cnt[id[k]], 1);
        }
    }
}

__global__ void offsets_k() {
    if (threadIdx.x == 0) {
        int run = 0;
        for (int e = 0; e < E; e++) { g_off[e] = run; g_cur[e] = run; run += g_cnt[e]; }
        g_off[E] = run;
    }
}

__global__ void scatter_k() {
    int a = blockIdx.x * blockDim.x + threadIdx.x;
    if (a < NA) {
        int e = g_topk_id[a];
        int pos = atomicAdd(&g_cur[e], 1);
        g_tok[pos] = a >> 3;
        g_ew [pos] = g_topk_w[a];
        g_pos[a]   = pos;
    }
}

// ---------------- MoE gate/up GEMM (3xTF32 mma) + SwiGLU + weight ----------
// grid (IM/64, 8, E), block 256 = 8 warps (4 m x 2 n). CTA tile 128 x 64.
__global__ __launch_bounds__(256) void moe_gateup_mma(const float* __restrict__ Wgate,
                                                      const float* __restrict__ Wup) {
    int e = blockIdx.z;
    int base = g_off[e], cnt = g_off[e + 1] - base;
    int t0 = blockIdx.y * 128;
    if (t0 >= cnt) return;
    int i0 = blockIdx.x * 64;
    __shared__ float As[2][128][20];   // [hi/lo][row][k] pad 16->20
    __shared__ float Bgs[2][KC][68];   // [hi/lo][k][col] pad 64->68
    __shared__ float Bus[2][KC][68];
    __shared__ int   stok[128];
    __shared__ float swt[128];
    int tid = threadIdx.x;
    if (tid < 128) {
        int r = t0 + tid;
        if (r < cnt) { stok[tid] = g_tok[base + r]; swt[tid] = g_ew[base + r]; }
        else         { stok[tid] = 0; swt[tid] = 0.f; }
    }
    __syncthreads();
    int wid = tid >> 5, lane = tid & 31;
    int wm = wid >> 1, wn = wid & 1;
    int lr = tid >> 1, lk = (tid & 1) * 8;   // A loader: row, k-offset
    int bkr = tid >> 4, bc = (tid & 15) * 4; // B loader: k-row, col
    const float* WgE = Wgate + (size_t)e * H * IM;
    const float* WuE = Wup   + (size_t)e * H * IM;
    float accg[2][4][4] = {};
    float accu[2][4][4] = {};
    for (int k0 = 0; k0 < H; k0 += KC) {
        // A: 128 rows x KC (gathered token rows)
        const float* src = g_hnorm + (size_t)stok[lr] * H + k0 + lk;
        float4 v0 = *(const float4*)(src);
        float4 v1 = *(const float4*)(src + 4);
        #pragma unroll
        for (int j = 0; j < 4; j++) {
            float hi, lo;
            split_tf(((const float*)&v0)[j], hi, lo);
            As[0][lr][lk + j] = hi; As[1][lr][lk + j] = lo;
            split_tf(((const float*)&v1)[j], hi, lo);
            As[0][lr][lk + 4 + j] = hi; As[1][lr][lk + 4 + j] = lo;
        }
        // B: KC x 64 for gate and up
        float4 g4 = *(const float4*)(WgE + (size_t)(k0 + bkr) * IM + i0 + bc);
        float4 u4 = *(const float4*)(WuE + (size_t)(k0 + bkr) * IM + i0 + bc);
        #pragma unroll
        for (int j = 0; j < 4; j++) {
            float hi, lo;
            split_tf(((const float*)&g4)[j], hi, lo);
            Bgs[0][bkr][bc + j] = hi; Bgs[1][bkr][bc + j] = lo;
            split_tf(((const float*)&u4)[j], hi, lo);
            Bus[0][bkr][bc + j] = hi; Bus[1][bkr][bc + j] = lo;
        }
        __syncthreads();
        #pragma unroll
        for (int kk = 0; kk < KC / 8; kk++) {
            int kx = kk * 8 + (lane & 3);
            unsigned ah[2][4], al[2][4];
            #pragma unroll
            for (int m = 0; m < 2; m++) {
                int r0 = wm * 32 + m * 16 + (lane >> 2);
                ah[m][0] = __float_as_uint(As[0][r0    ][kx    ]);
                ah[m][1] = __float_as_uint(As[0][r0 + 8][kx    ]);
                ah[m][2] = __float_as_uint(As[0][r0    ][kx + 4]);
                ah[m][3] = __float_as_uint(As[0][r0 + 8][kx + 4]);
                al[m][0] = __float_as_uint(As[1][r0    ][kx    ]);
                al[m][1] = __float_as_uint(As[1][r0 + 8][kx    ]);
                al[m][2] = __float_as_uint(As[1][r0    ][kx + 4]);
                al[m][3] = __float_as_uint(As[1][r0 + 8][kx + 4]);
            }
            #pragma unroll
            for (int n = 0; n < 4; n++) {
                int col = wn * 32 + n * 8 + (lane >> 2);
                unsigned bh[2] = { __float_as_uint(Bgs[0][kx][col]), __float_as_uint(Bgs[0][kx + 4][col]) };
                unsigned bl[2] = { __float_as_uint(Bgs[1][kx][col]), __float_as_uint(Bgs[1][kx + 4][col]) };
                unsigned uh[2] = { __float_as_uint(Bus[0][kx][col]), __float_as_uint(Bus[0][kx + 4][col]) };
                unsigned ul[2] = { __float_as_uint(Bus[1][kx][col]), __float_as_uint(Bus[1][kx + 4][col]) };
                #pragma unroll
                for (int m = 0; m < 2; m++) {
                    mma_tf32(accg[m][n], ah[m], bh);
                    mma_tf32(accg[m][n], ah[m], bl);
                    mma_tf32(accg[m][n], al[m], bh);
                    mma_tf32(accu[m][n], ah[m], uh);
                    mma_tf32(accu[m][n], ah[m], ul);
                    mma_tf32(accu[m][n], al[m], uh);
                }
            }
        }
        __syncthreads();
    }
    // epilogue: silu(g)*u*combine -> grouped g_act rows
    #pragma unroll
    for (int m = 0; m < 2; m++)
        #pragma unroll
        for (int n = 0; n < 4; n++)
            #pragma unroll
            for (int r = 0; r < 4; r++) {
                int row = wm * 32 + m * 16 + (lane >> 2) + ((r >= 2) ? 8 : 0);
                int col = wn * 32 + n * 8 + (lane & 3) * 2 + (r & 1);
                int gr = t0 + row;
                if (gr < cnt) {
                    float gg = accg[m][n][r], uu = accu[m][n][r];
                    float a = (gg / (1.f + __expf(-gg))) * uu * swt[row];
                    g_act[(size_t)(base + gr) * IM + i0 + col] = a;
                }
            }
}

// ---------------- MoE down GEMM (3xTF32 mma) -> grouped partial rows -------
// grid (H/64, 8, E), block 256. CTA tile 128 x 64, K = IM = 768.
__global__ __launch_bounds__(256) void moe_down_mma(const float* __restrict__ Wdown) {
    int e = blockIdx.z;
    int base = g_off[e], cnt = g_off[e + 1] - base;
    int t0 = blockIdx.y * 128;
    if (t0 >= cnt) return;
    int h0 = blockIdx.x * 64;
    __shared__ float As[2][128][20];
    __shared__ float Bs[2][KC][68];
    int tid = threadIdx.x;
    int wid = tid >> 5, lane = tid & 31;
    int wm = wid >> 1, wn = wid & 1;
    int lr = tid >> 1, lk = (tid & 1) * 8;
    int bkr = tid >> 4, bc = (tid & 15) * 4;
    int ar = t0 + lr; if (ar >= cnt) ar = t0;   // clamp to a valid grouped row
    const float* WdE = Wdown + (size_t)e * IM * H;
    const float* arow = g_act + (size_t)(base + ar) * IM;
    float acc[2][4][4] = {};
    for (int k0 = 0; k0 < IM; k0 += KC) {
        float4 v0 = *(const float4*)(arow + k0 + lk);
        float4 v1 = *(const float4*)(arow + k0 + lk + 4);
        #pragma unroll
        for (int j = 0; j < 4; j++) {
            float hi, lo;
            split_tf(((const float*)&v0)[j], hi, lo);
            As[0][lr][lk + j] = hi; As[1][lr][lk + j] = lo;
            split_tf(((const float*)&v1)[j], hi, lo);
            As[0][lr][lk + 4 + j] = hi; As[1][lr][lk + 4 + j] = lo;
        }
        float4 b4 = *(const float4*)(WdE + (size_t)(k0 + bkr) * H + h0 + bc);
        #pragma unroll
        for (int j = 0; j < 4; j++) {
            float hi, lo;
            split_tf(((const float*)&b4)[j], hi, lo);
            Bs[0][bkr][bc + j] = hi; Bs[1][bkr][bc + j] = lo;
        }
        __syncthreads();
        #pragma unroll
        for (int kk = 0; kk < KC / 8; kk++) {
            int kx = kk * 8 + (lane & 3);
            unsigned ah[2][4], al[2][4];
            #pragma unroll
            for (int m = 0; m < 2; m++) {
                int r0 = wm * 32 + m * 16 + (lane >> 2);
                ah[m][0] = __float_as_uint(As[0][r0    ][kx    ]);
                ah[m][1] = __float_as_uint(As[0][r0 + 8][kx    ]);
                ah[m][2] = __float_as_uint(As[0][r0    ][kx + 4]);
                ah[m][3] = __float_as_uint(As[0][r0 + 8][kx + 4]);
                al[m][0] = __float_as_uint(As[1][r0    ][kx    ]);
                al[m][1] = __float_as_uint(As[1][r0 + 8][kx    ]);
                al[m][2] = __float_as_uint(As[1][r0    ][kx + 4]);
                al[m][3] = __float_as_uint(As[1][r0 + 8][kx + 4]);
            }
            #pragma unroll
            for (int n = 0; n < 4; n++) {
                int col = wn * 32 + n * 8 + (lane >> 2);
                unsigned bh[2] = { __float_as_uint(Bs[0][kx][col]), __float_as_uint(Bs[0][kx + 4][col]) };
                unsigned bl[2] = { __float_as_uint(Bs[1][kx][col]), __float_as_uint(Bs[1][kx + 4][col]) };
                #pragma unroll
                for (int m = 0; m < 2; m++) {
                    mma_tf32(acc[m][n], ah[m], bh);
                    mma_tf32(acc[m][n], ah[m], bl);
                    mma_tf32(acc[m][n], al[m], bh);
                }
            }
        }
        __syncthreads();
    }
    #pragma unroll
    for (int m = 0; m < 2; m++)
        #pragma unroll
        for (int n = 0; n < 4; n++)
            #pragma unroll
            for (int r = 0; r < 4; r++) {
                int row = wm * 32 + m * 16 + (lane >> 2) + ((r >= 2) ? 8 : 0);
                int col = wn * 32 + n * 8 + (lane & 3) * 2 + (r & 1);
                int gr = t0 + row;
                if (gr < cnt)
                    g_part[(size_t)(base + gr) * H + h0 + col] = acc[m][n][r];
            }
}

// ---------------- finalize: residual + sum of 8 grouped partial rows -------
__global__ void finalize_k(float* __restrict__ out) {
    size_t idx = (size_t)blockIdx.x * 256 + threadIdx.x;   // S*H total
    int t = (int)(idx >> 11);
    int hc = (int)(idx & 2047);
    float v = g_hid2[idx];
    #pragma unroll
    for (int k = 0; k < TK; k++)
        v += g_part[(size_t)g_pos[t * TK + k] * H + hc];
    out[idx] = v;
}

// ---------------- launch ----------------
extern "C" void kernel_launch(void* const* d_in, const int* in_sizes, int n_in,
                              void* d_out, int out_size) {
    const float* hidden = (const float*)d_in[0];
    const float* ln1_g  = (const float*)d_in[1];
    const float* ln2_g  = (const float*)d_in[2];
    const float* Wq     = (const float*)d_in[3];
    const float* Wk     = (const float*)d_in[4];
    const float* Wv     = (const float*)d_in[5];
    const float* Wo     = (const float*)d_in[6];
    const float* Wg     = (const float*)d_in[7];
    const float* Wgate  = (const float*)d_in[8];
    const float* Wup    = (const float*)d_in[9];
    const float* Wdown  = (const float*)d_in[10];
    float* out = (float*)d_out;

    // 1. input RMSNorm -> buf0 (xnorm)
    rmsnorm_k<<<S, 256>>>(hidden, -1, ln1_g, 0);
    // 2. QKV projections: A=xnorm(0) -> q(1), k(2), v(3)
    sgemm64<<<dim3((NH * D) / 64, S / 64), 256>>>(0, Wq, nullptr, 1, S, NH * D, H);
    sgemm64<<<dim3((NKV * D) / 64, S / 64), 256>>>(0, Wk, nullptr, 2, S, NKV * D, H);
    sgemm64<<<dim3((NKV * D) / 64, S / 64), 256>>>(0, Wv, nullptr, 3, S, NKV * D, H);
    // 3. causal GQA attention -> ctx(4)
    attn_k<<<dim3(S / 64, NH), 256>>>();
    // 4. output projection + residual: A=ctx(4), res=hidden -> hid2(5)
    sgemm64<<<dim3(H / 64, S / 64), 256>>>(4, Wo, hidden, 5, S, H, NH * D);
    // 5. post-attn RMSNorm: hid2(5) -> hnorm(6)
    rmsnorm_k<<<S, 256>>>(nullptr, 5, ln2_g, 6);
    // 6. router + dispatch
    zero_cnt_k<<<1, 64>>>();
    router_k<<<S, 64>>>(Wg);
    offsets_k<<<1, 1>>>();
    scatter_k<<<(NA + 255) / 256, 256>>>();
    // 7. expert gate/up + SwiGLU via tensor cores (3xTF32)
    moe_gateup_mma<<<dim3(IM / 64, 8, E), 256>>>(Wgate, Wup);
    // 8. expert down-proj via tensor cores (3xTF32)
    moe_down_mma<<<dim3(H / 64, 8, E), 256>>>(Wdown);
    // 9. residual + combine
    finalize_k<<<(S * H) / 256, 256>>>(out);
    (void)in_sizes; (void)n_in; (void)out_size;
}

// round 5
// speedup vs baseline: 1.7807x; 1.6172x over previous
#include <cuda_runtime.h>
#include <cuda_bf16.h>
#include <math.h>

// Problem constants
constexpr int S   = 1024;   // tokens
constexpr int H   = 2048;   // hidden
constexpr int NH  = 16;     // q heads
constexpr int NKV = 4;      // kv heads
constexpr int D   = 128;    // head dim
constexpr int E   = 64;     // experts
constexpr int TK  = 8;      // top_k
constexpr int IM  = 768;    // moe intermediate
constexpr float EPS = 1e-6f;
constexpr int NA = S * TK;  // total assignments = 8192
constexpr int KC = 32;      // MMA K-chunk
constexpr int SP = 40;      // smem k-stride (bf16 elems): 16B-aligned rows, ldmatrix conflict-free

// ---------------- scratch (device globals; no allocation allowed) ----------
__device__ float g_xnorm [S * H];
__device__ float g_q     [S * NH * D];
__device__ float g_k     [S * NKV * D];
__device__ float g_v     [S * NKV * D];
__device__ float g_ctx   [S * NH * D];
__device__ float g_hid2  [S * H];
__device__ float g_hnorm [S * H];
__device__ int   g_topk_id[NA];
__device__ float g_topk_w [NA];
__device__ int   g_cnt   [E];
__device__ int   g_off   [E + 1];
__device__ int   g_cur   [E];
__device__ int   g_tok   [NA];     // expert-grouped token index
__device__ float g_ew    [NA];     // expert-grouped combine weight
__device__ int   g_pos   [NA];     // assignment a -> expert-grouped row
__device__ float g_act   [NA * IM];        // grouped weighted SwiGLU activations
__device__ float g_part  [(size_t)NA * H]; // grouped down-proj rows

__device__ __forceinline__ float* bufptr(int b) {
    switch (b) {
        case 0: return g_xnorm;
        case 1: return g_q;
        case 2: return g_k;
        case 3: return g_v;
        case 4: return g_ctx;
        case 5: return g_hid2;
        case 6: return g_hnorm;
    }
    return nullptr;
}

// ---------------- bf16 / mma helpers ----------------
__device__ __forceinline__ void split_bf(float v, __nv_bfloat16& hi, __nv_bfloat16& lo) {
    hi = __float2bfloat16(v);
    lo = __float2bfloat16(v - __bfloat162float(hi));
}
__device__ __forceinline__ unsigned smaddr(const void* p) {
    return (unsigned)__cvta_generic_to_shared(p);
}
__device__ __forceinline__ void ldsm_x4(unsigned r[4], unsigned a) {
    asm volatile("ldmatrix.sync.aligned.m8n8.x4.shared.b16 {%0,%1,%2,%3}, [%4];"
        : "=r"(r[0]), "=r"(r[1]), "=r"(r[2]), "=r"(r[3]) : "r"(a));
}
__device__ __forceinline__ void mma_bf16(float c[4], const unsigned a[4], const unsigned b[2]) {
    asm volatile(
        "mma.sync.aligned.m16n8k16.row.col.f32.bf16.bf16.f32 "
        "{%0,%1,%2,%3}, {%4,%5,%6,%7}, {%8,%9}, {%0,%1,%2,%3};\n"
        : "+f"(c[0]), "+f"(c[1]), "+f"(c[2]), "+f"(c[3])
        : "r"(a[0]), "r"(a[1]), "r"(a[2]), "r"(a[3]), "r"(b[0]), "r"(b[1]));
}
// A-frag ldmatrix address: As[row][k] (stride SP), tile at (r0, k0)
__device__ __forceinline__ unsigned a_addr(const __nv_bfloat16* As, int r0, int k0, int lane) {
    int row = r0 + (lane & 15);
    int col = k0 + (lane >> 4) * 8;
    return smaddr(As + row * SP + col);
}
// B-frag ldmatrix address: Bs[n][k] (stride SP), two n-blocks at (n0, k0)
__device__ __forceinline__ unsigned b_addr(const __nv_bfloat16* Bs, int n0, int k0, int lane) {
    int row = n0 + (lane & 7) + ((lane & 16) ? 8 : 0);
    int col = k0 + (lane & 8);
    return smaddr(Bs + row * SP + col);
}

// ---------------- RMSNorm ----------------
__global__ void rmsnorm_k(const float* __restrict__ x_ext, int xBuf,
                          const float* __restrict__ g, int outBuf) {
    const float* x = x_ext ? x_ext : bufptr(xBuf);
    float* out = bufptr(outBuf);
    int row = blockIdx.x, tid = threadIdx.x;
    const float* xr = x + (size_t)row * H;
    float ss = 0.f;
    for (int j = tid; j < H; j += 256) { float v = xr[j]; ss += v * v; }
    for (int o = 16; o; o >>= 1) ss += __shfl_xor_sync(0xffffffffu, ss, o);
    __shared__ float red[8];
    if ((tid & 31) == 0) red[tid >> 5] = ss;
    __syncthreads();
    if (tid < 32) {
        float v = (tid < 8) ? red[tid] : 0.f;
        for (int o = 4; o; o >>= 1) v += __shfl_xor_sync(0xffffffffu, v, o);
        if (tid == 0) red[0] = v;
    }
    __syncthreads();
    float inv = rsqrtf(red[0] / (float)H + EPS);
    for (int j = tid; j < H; j += 256) out[(size_t)row * H + j] = xr[j] * inv * g[j];
}

// ---------------- dense bf16-3term MMA GEMM: C = (res?) + A @ B ------------
// CTA tile 128x64, 8 warps (4m x 2n), warp tile 32x32. M=1024 fixed rows.
__global__ __launch_bounds__(256) void dense_mma(int aBuf,
                                                 const float* __restrict__ B,
                                                 const float* __restrict__ res,
                                                 int cBuf, int N, int K) {
    const float* A = bufptr(aBuf);
    float* C = bufptr(cBuf);
    int n0c = blockIdx.x * 64, m0c = blockIdx.y * 128;
    __shared__ __align__(16) __nv_bfloat16 As_hi[128 * SP], As_lo[128 * SP];
    __shared__ __align__(16) __nv_bfloat16 Bs_hi[64 * SP],  Bs_lo[64 * SP];
    int tid = threadIdx.x;
    int wid = tid >> 5, lane = tid & 31;
    int wm = wid >> 1, wn = wid & 1;
    int lr = tid >> 1, lk = (tid & 1) * 16;       // A loader
    int bn4 = (tid & 15) * 4, bkp = tid >> 4;     // B loader: k-pair 0..15
    float acc[2][4][4] = {};
    for (int k0 = 0; k0 < K; k0 += KC) {
        // A: 128 x KC
        const float* src = A + (size_t)(m0c + lr) * K + k0 + lk;
        #pragma unroll
        for (int q = 0; q < 4; q++) {
            float4 v = *(const float4*)(src + q * 4);
            #pragma unroll
            for (int j = 0; j < 4; j++) {
                __nv_bfloat16 hi, lo;
                split_bf(((const float*)&v)[j], hi, lo);
                As_hi[lr * SP + lk + q * 4 + j] = hi;
                As_lo[lr * SP + lk + q * 4 + j] = lo;
            }
        }
        // B: KC x 64 -> transposed smem [n][k]
        {
            const float* b0 = B + (size_t)(k0 + 2 * bkp) * N + n0c + bn4;
            float4 v0 = *(const float4*)(b0);
            float4 v1 = *(const float4*)(b0 + N);
            #pragma unroll
            for (int j = 0; j < 4; j++) {
                int n = bn4 + j;
                __nv_bfloat16 h0, l0, h1, l1;
                split_bf(((const float*)&v0)[j], h0, l0);
                split_bf(((const float*)&v1)[j], h1, l1);
                *(__nv_bfloat162*)&Bs_hi[n * SP + 2 * bkp] = __nv_bfloat162(h0, h1);
                *(__nv_bfloat162*)&Bs_lo[n * SP + 2 * bkp] = __nv_bfloat162(l0, l1);
            }
        }
        __syncthreads();
        #pragma unroll
        for (int ks = 0; ks < KC / 16; ks++) {
            int kk = ks * 16;
            unsigned Ah[2][4], Al[2][4];
            #pragma unroll
            for (int m = 0; m < 2; m++) {
                ldsm_x4(Ah[m], a_addr(As_hi, wm * 32 + m * 16, kk, lane));
                ldsm_x4(Al[m], a_addr(As_lo, wm * 32 + m * 16, kk, lane));
            }
            #pragma unroll
            for (int np = 0; np < 2; np++) {
                int n0 = wn * 32 + np * 16;
                unsigned Bh[4], Bl[4];
                ldsm_x4(Bh, b_addr(Bs_hi, n0, kk, lane));
                ldsm_x4(Bl, b_addr(Bs_lo, n0, kk, lane));
                #pragma unroll
                for (int m = 0; m < 2; m++)
                    #pragma unroll
                    for (int h = 0; h < 2; h++) {
                        float* c = acc[m][np * 2 + h];
                        mma_bf16(c, Ah[m], Bh + 2 * h);
                        mma_bf16(c, Ah[m], Bl + 2 * h);
                        mma_bf16(c, Al[m], Bh + 2 * h);
                    }
            }
        }
        __syncthreads();
    }
    #pragma unroll
    for (int m = 0; m < 2; m++)
        #pragma unroll
        for (int n = 0; n < 4; n++)
            #pragma unroll
            for (int r = 0; r < 4; r++) {
                int row = m0c + wm * 32 + m * 16 + (lane >> 2) + ((r >= 2) ? 8 : 0);
                int col = n0c + wn * 32 + n * 8 + (lane & 3) * 2 + (r & 1);
                size_t idx = (size_t)row * N + col;
                float v = acc[m][n][r];
                if (res) v += res[idx];
                C[idx] = v;
            }
}

// ---------------- causal flash attention (fp32) ----------------
__global__ __launch_bounds__(256) void attn_k() {
    constexpr int QT = 64, KT = 32;
    constexpr float SC = 0.0883883476483184f; // 1/sqrt(128)
    int qt = blockIdx.x, h = blockIdx.y;
    int kvh = h / (NH / NKV);
    int tid = threadIdx.x;
    int qi = tid >> 2, qr = tid & 3;
    int qrow = qt * QT + qi;
    int d0 = qr * 32;
    __shared__ float Ks[KT][D];
    __shared__ float Vs[KT][D];
    float qreg[32], acc[32];
    #pragma unroll
    for (int d = 0; d < 32; d++) {
        qreg[d] = g_q[(size_t)qrow * (NH * D) + h * D + d0 + d] * SC;
        acc[d] = 0.f;
    }
    float m = -1e30f, l = 0.f;
    int ktiles = qt * 2 + 2;
    for (int kt = 0; kt < ktiles; kt++) {
        int kb = kt * KT;
        for (int idx = tid; idx < KT * D; idx += 256) {
            int r = idx >> 7, c = idx & 127;
            Ks[r][c] = g_k[(size_t)(kb + r) * (NKV * D) + kvh * D + c];
            Vs[r][c] = g_v[(size_t)(kb + r) * (NKV * D) + kvh * D + c];
        }
        __syncthreads();
        float sc[KT];
        #pragma unroll
        for (int j = 0; j < KT; j++) {
            float p = 0.f;
            #pragma unroll
            for (int d = 0; d < 32; d++) p += qreg[d] * Ks[j][d0 + d];
            p += __shfl_xor_sync(0xffffffffu, p, 1);
            p += __shfl_xor_sync(0xffffffffu, p, 2);
            sc[j] = (kb + j <= qrow) ? p : -1e30f;
        }
        float tm = m;
        #pragma unroll
        for (int j = 0; j < KT; j++) tm = fmaxf(tm, sc[j]);
        float corr = __expf(m - tm);
        m = tm;
        l *= corr;
        #pragma unroll
        for (int d = 0; d < 32; d++) acc[d] *= corr;
        #pragma unroll
        for (int j = 0; j < KT; j++) {
            float p = __expf(sc[j] - m);
            l += p;
            #pragma unroll
            for (int d = 0; d < 32; d++) acc[d] += p * Vs[j][d0 + d];
        }
        __syncthreads();
    }
    float inv = 1.f / l;
    #pragma unroll
    for (int d = 0; d < 32; d++)
        g_ctx[(size_t)qrow * (NH * D) + h * D + d0 + d] = acc[d] * inv;
}

// ---------------- router: logits, softmax-top8, counts ----------------
__global__ void zero_cnt_k() { if (threadIdx.x < E) g_cnt[threadIdx.x] = 0; }

__global__ void router_k(const float* __restrict__ Wg) {
    int t = blockIdx.x, tid = threadIdx.x;   // blockDim = 64
    __shared__ float sh[H];
    __shared__ float lg[E];
    for (int j = tid; j < H; j += 64) sh[j] = g_hnorm[(size_t)t * H + j];
    __syncthreads();
    float lo = 0.f;
    for (int j = 0; j < H; j++) lo += sh[j] * Wg[(size_t)j * E + tid];
    lg[tid] = lo;
    __syncthreads();
    if (tid == 0) {
        float tmp[E];
        for (int e = 0; e < E; e++) tmp[e] = lg[e];
        int   id[TK]; float w[TK];
        for (int k = 0; k < TK; k++) {
            int best = 0; float bv = tmp[0];
            for (int e = 1; e < E; e++) if (tmp[e] > bv) { bv = tmp[e]; best = e; }
            id[k] = best; w[k] = bv; tmp[best] = -1e30f;
        }
        float mx = w[0], s = 0.f;
        for (int k = 0; k < TK; k++) { w[k] = expf(w[k] - mx); s += w[k]; }
        float inv = 1.f / s;
        for (int k = 0; k < TK; k++) {
            g_topk_id[t * TK + k] = id[k];
            g_topk_w [t * TK + k] = w[k] * inv;
            atomicAdd(&g_cnt[id[k]], 1);
        }
    }
}

__global__ void offsets_k() {
    if (threadIdx.x == 0) {
        int run = 0;
        for (int e = 0; e < E; e++) { g_off[e] = run; g_cur[e] = run; run += g_cnt[e]; }
        g_off[E] = run;
    }
}

__global__ void scatter_k() {
    int a = blockIdx.x * blockDim.x + threadIdx.x;
    if (a < NA) {
        int e = g_topk_id[a];
        int pos = atomicAdd(&g_cur[e], 1);
        g_tok[pos] = a >> 3;
        g_ew [pos] = g_topk_w[a];
        g_pos[a]   = pos;
    }
}

// ---------------- MoE gate/up GEMM (bf16 3-term) + SwiGLU + weight ---------
// grid (IM/64, 8, E), block 256. CTA tile 128 x 64.
__global__ __launch_bounds__(256) void moe_gateup_mma(const float* __restrict__ Wgate,
                                                      const float* __restrict__ Wup) {
    int e = blockIdx.z;
    int base = g_off[e], cnt = g_off[e + 1] - base;
    int t0 = blockIdx.y * 128;
    if (t0 >= cnt) return;
    int i0 = blockIdx.x * 64;
    __shared__ __align__(16) __nv_bfloat16 As_hi[128 * SP], As_lo[128 * SP];
    __shared__ __align__(16) __nv_bfloat16 Gh_s[64 * SP], Gl_s[64 * SP];
    __shared__ __align__(16) __nv_bfloat16 Uh_s[64 * SP], Ul_s[64 * SP];
    __shared__ int   stok[128];
    __shared__ float swt[128];
    int tid = threadIdx.x;
    if (tid < 128) {
        int r = t0 + tid;
        if (r < cnt) { stok[tid] = g_tok[base + r]; swt[tid] = g_ew[base + r]; }
        else         { stok[tid] = 0; swt[tid] = 0.f; }
    }
    __syncthreads();
    int wid = tid >> 5, lane = tid & 31;
    int wm = wid >> 1, wn = wid & 1;
    int lr = tid >> 1, lk = (tid & 1) * 16;
    int bn4 = (tid & 15) * 4, bkp = tid >> 4;
    const float* WgE = Wgate + (size_t)e * H * IM;
    const float* WuE = Wup   + (size_t)e * H * IM;
    float accg[2][4][4] = {};
    float accu[2][4][4] = {};
    for (int k0 = 0; k0 < H; k0 += KC) {
        const float* src = g_hnorm + (size_t)stok[lr] * H + k0 + lk;
        #pragma unroll
        for (int q = 0; q < 4; q++) {
            float4 v = *(const float4*)(src + q * 4);
            #pragma unroll
            for (int j = 0; j < 4; j++) {
                __nv_bfloat16 hi, lo;
                split_bf(((const float*)&v)[j], hi, lo);
                As_hi[lr * SP + lk + q * 4 + j] = hi;
                As_lo[lr * SP + lk + q * 4 + j] = lo;
            }
        }
        {
            const float* gp = WgE + (size_t)(k0 + 2 * bkp) * IM + i0 + bn4;
            const float* up = WuE + (size_t)(k0 + 2 * bkp) * IM + i0 + bn4;
            float4 g0 = *(const float4*)(gp);
            float4 g1 = *(const float4*)(gp + IM);
            float4 u0 = *(const float4*)(up);
            float4 u1 = *(const float4*)(up + IM);
            #pragma unroll
            for (int j = 0; j < 4; j++) {
                int n = bn4 + j;
                __nv_bfloat16 h0, l0, h1, l1;
                split_bf(((const float*)&g0)[j], h0, l0);
                split_bf(((const float*)&g1)[j], h1, l1);
                *(__nv_bfloat162*)&Gh_s[n * SP + 2 * bkp] = __nv_bfloat162(h0, h1);
                *(__nv_bfloat162*)&Gl_s[n * SP + 2 * bkp] = __nv_bfloat162(l0, l1);
                split_bf(((const float*)&u0)[j], h0, l0);
                split_bf(((const float*)&u1)[j], h1, l1);
                *(__nv_bfloat162*)&Uh_s[n * SP + 2 * bkp] = __nv_bfloat162(h0, h1);
                *(__nv_bfloat162*)&Ul_s[n * SP + 2 * bkp] = __nv_bfloat162(l0, l1);
            }
        }
        __syncthreads();
        #pragma unroll
        for (int ks = 0; ks < KC / 16; ks++) {
            int kk = ks * 16;
            unsigned Ah[2][4], Al[2][4];
            #pragma unroll
            for (int m = 0; m < 2; m++) {
                ldsm_x4(Ah[m], a_addr(As_hi, wm * 32 + m * 16, kk, lane));
                ldsm_x4(Al[m], a_addr(As_lo, wm * 32 + m * 16, kk, lane));
            }
            #pragma unroll
            for (int np = 0; np < 2; np++) {
                int n0 = wn * 32 + np * 16;
                unsigned Gh[4], Gl[4], Uh[4], Ul[4];
                ldsm_x4(Gh, b_addr(Gh_s, n0, kk, lane));
                ldsm_x4(Gl, b_addr(Gl_s, n0, kk, lane));
                ldsm_x4(Uh, b_addr(Uh_s, n0, kk, lane));
                ldsm_x4(Ul, b_addr(Ul_s, n0, kk, lane));
                #pragma unroll
                for (int m = 0; m < 2; m++)
                    #pragma unroll
                    for (int h = 0; h < 2; h++) {
                        float* cg = accg[m][np * 2 + h];
                        mma_bf16(cg, Ah[m], Gh + 2 * h);
                        mma_bf16(cg, Ah[m], Gl + 2 * h);
                        mma_bf16(cg, Al[m], Gh + 2 * h);
                        float* cu = accu[m][np * 2 + h];
                        mma_bf16(cu, Ah[m], Uh + 2 * h);
                        mma_bf16(cu, Ah[m], Ul + 2 * h);
                        mma_bf16(cu, Al[m], Uh + 2 * h);
                    }
            }
        }
        __syncthreads();
    }
    #pragma unroll
    for (int m = 0; m < 2; m++)
        #pragma unroll
        for (int n = 0; n < 4; n++)
            #pragma unroll
            for (int r = 0; r < 4; r++) {
                int row = wm * 32 + m * 16 + (lane >> 2) + ((r >= 2) ? 8 : 0);
                int col = wn * 32 + n * 8 + (lane & 3) * 2 + (r & 1);
                int gr = t0 + row;
                if (gr < cnt) {
                    float gg = accg[m][n][r], uu = accu[m][n][r];
                    float a = (gg / (1.f + __expf(-gg))) * uu * swt[row];
                    g_act[(size_t)(base + gr) * IM + i0 + col] = a;
                }
            }
}

// ---------------- MoE down GEMM (bf16 3-term) -> grouped partial rows ------
// grid (H/64, 8, E), block 256. CTA tile 128 x 64, K = IM = 768.
__global__ __launch_bounds__(256) void moe_down_mma(const float* __restrict__ Wdown) {
    int e = blockIdx.z;
    int base = g_off[e], cnt = g_off[e + 1] - base;
    int t0 = blockIdx.y * 128;
    if (t0 >= cnt) return;
    int h0 = blockIdx.x * 64;
    __shared__ __align__(16) __nv_bfloat16 As_hi[128 * SP], As_lo[128 * SP];
    __shared__ __align__(16) __nv_bfloat16 Bs_hi[64 * SP],  Bs_lo[64 * SP];
    int tid = threadIdx.x;
    int wid = tid >> 5, lane = tid & 31;
    int wm = wid >> 1, wn = wid & 1;
    int lr = tid >> 1, lk = (tid & 1) * 16;
    int bn4 = (tid & 15) * 4, bkp = tid >> 4;
    int ar = t0 + lr; if (ar >= cnt) ar = cnt - 1;
    const float* WdE = Wdown + (size_t)e * IM * H;
    const float* arow = g_act + (size_t)(base + ar) * IM;
    float acc[2][4][4] = {};
    for (int k0 = 0; k0 < IM; k0 += KC) {
        #pragma unroll
        for (int q = 0; q < 4; q++) {
            float4 v = *(const float4*)(arow + k0 + lk + q * 4);
            #pragma unroll
            for (int j = 0; j < 4; j++) {
                __nv_bfloat16 hi, lo;
                split_bf(((const float*)&v)[j], hi, lo);
                As_hi[lr * SP + lk + q * 4 + j] = hi;
                As_lo[lr * SP + lk + q * 4 + j] = lo;
            }
        }
        {
            const float* bp = WdE + (size_t)(k0 + 2 * bkp) * H + h0 + bn4;
            float4 v0 = *(const float4*)(bp);
            float4 v1 = *(const float4*)(bp + H);
            #pragma unroll
            for (int j = 0; j < 4; j++) {
                int n = bn4 + j;
                __nv_bfloat16 h0b, l0b, h1b, l1b;
                split_bf(((const float*)&v0)[j], h0b, l0b);
                split_bf(((const float*)&v1)[j], h1b, l1b);
                *(__nv_bfloat162*)&Bs_hi[n * SP + 2 * bkp] = __nv_bfloat162(h0b, h1b);
                *(__nv_bfloat162*)&Bs_lo[n * SP + 2 * bkp] = __nv_bfloat162(l0b, l1b);
            }
        }
        __syncthreads();
        #pragma unroll
        for (int ks = 0; ks < KC / 16; ks++) {
            int kk = ks * 16;
            unsigned Ah[2][4], Al[2][4];
            #pragma unroll
            for (int m = 0; m < 2; m++) {
                ldsm_x4(Ah[m], a_addr(As_hi, wm * 32 + m * 16, kk, lane));
                ldsm_x4(Al[m], a_addr(As_lo, wm * 32 + m * 16, kk, lane));
            }
            #pragma unroll
            for (int np = 0; np < 2; np++) {
                int n0 = wn * 32 + np * 16;
                unsigned Bh[4], Bl[4];
                ldsm_x4(Bh, b_addr(Bs_hi, n0, kk, lane));
                ldsm_x4(Bl, b_addr(Bs_lo, n0, kk, lane));
                #pragma unroll
                for (int m = 0; m < 2; m++)
                    #pragma unroll
                    for (int h = 0; h < 2; h++) {
                        float* c = acc[m][np * 2 + h];
                        mma_bf16(c, Ah[m], Bh + 2 * h);
                        mma_bf16(c, Ah[m], Bl + 2 * h);
                        mma_bf16(c, Al[m], Bh + 2 * h);
                    }
            }
        }
        __syncthreads();
    }
    #pragma unroll
    for (int m = 0; m < 2; m++)
        #pragma unroll
        for (int n = 0; n < 4; n++)
            #pragma unroll
            for (int r = 0; r < 4; r++) {
                int row = wm * 32 + m * 16 + (lane >> 2) + ((r >= 2) ? 8 : 0);
                int col = wn * 32 + n * 8 + (lane & 3) * 2 + (r & 1);
                int gr = t0 + row;
                if (gr < cnt)
                    g_part[(size_t)(base + gr) * H + h0 + col] = acc[m][n][r];
            }
}

// ---------------- finalize: residual + sum of 8 grouped partial rows -------
__global__ void finalize_k(float* __restrict__ out) {
    size_t idx = (size_t)blockIdx.x * 256 + threadIdx.x;   // S*H total
    int t = (int)(idx >> 11);
    int hc = (int)(idx & 2047);
    float v = g_hid2[idx];
    #pragma unroll
    for (int k = 0; k < TK; k++)
        v += g_part[(size_t)g_pos[t * TK + k] * H + hc];
    out[idx] = v;
}

// ---------------- launch ----------------
extern "C" void kernel_launch(void* const* d_in, const int* in_sizes, int n_in,
                              void* d_out, int out_size) {
    const float* hidden = (const float*)d_in[0];
    const float* ln1_g  = (const float*)d_in[1];
    const float* ln2_g  = (const float*)d_in[2];
    const float* Wq     = (const float*)d_in[3];
    const float* Wk     = (const float*)d_in[4];
    const float* Wv     = (const float*)d_in[5];
    const float* Wo     = (const float*)d_in[6];
    const float* Wg     = (const float*)d_in[7];
    const float* Wgate  = (const float*)d_in[8];
    const float* Wup    = (const float*)d_in[9];
    const float* Wdown  = (const float*)d_in[10];
    float* out = (float*)d_out;

    // 1. input RMSNorm -> buf0 (xnorm)
    rmsnorm_k<<<S, 256>>>(hidden, -1, ln1_g, 0);
    // 2. QKV projections (bf16 3-term tensor MMA)
    dense_mma<<<dim3((NH * D) / 64, S / 128), 256>>>(0, Wq, nullptr, 1, NH * D, H);
    dense_mma<<<dim3((NKV * D) / 64, S / 128), 256>>>(0, Wk, nullptr, 2, NKV * D, H);
    dense_mma<<<dim3((NKV * D) / 64, S / 128), 256>>>(0, Wv, nullptr, 3, NKV * D, H);
    // 3. causal GQA attention -> ctx(4)
    attn_k<<<dim3(S / 64, NH), 256>>>();
    // 4. output projection + residual
    dense_mma<<<dim3(H / 64, S / 128), 256>>>(4, Wo, hidden, 5, H, NH * D);
    // 5. post-attn RMSNorm
    rmsnorm_k<<<S, 256>>>(nullptr, 5, ln2_g, 6);
    // 6. router + dispatch
    zero_cnt_k<<<1, 64>>>();
    router_k<<<S, 64>>>(Wg);
    offsets_k<<<1, 1>>>();
    scatter_k<<<(NA + 255) / 256, 256>>>();
    // 7. expert gate/up + SwiGLU
    moe_gateup_mma<<<dim3(IM / 64, 8, E), 256>>>(Wgate, Wup);
    // 8. expert down-proj
    moe_down_mma<<<dim3(H / 64, 8, E), 256>>>(Wdown);
    // 9. residual + combine
    finalize_k<<<(S * H) / 256, 256>>>(out);
    (void)in_sizes; (void)n_in; (void)out_size;
}

// round 6
// speedup vs baseline: 2.2190x; 1.2462x over previous
#include <cuda_runtime.h>
#include <math.h>

// Problem constants
constexpr int S   = 1024;   // tokens
constexpr int H   = 2048;   // hidden
constexpr int NH  = 16;     // q heads
constexpr int NKV = 4;      // kv heads
constexpr int D   = 128;    // head dim
constexpr int E   = 64;     // experts
constexpr int TK  = 8;      // top_k
constexpr int IM  = 768;    // moe intermediate
constexpr float EPS = 1e-6f;
constexpr int NA = S * TK;  // total assignments = 8192
constexpr int KC  = 16;     // GEMM K-chunk
constexpr int AST = 20;     // A smem stride (floats): conflict-free, 80B rows
constexpr int BST = 72;     // B smem stride (floats): conflict-free, 288B rows

// ---------------- scratch (device globals; no allocation allowed) ----------
__device__ float g_xnorm [S * H];
__device__ float g_q     [S * NH * D];
__device__ float g_k     [S * NKV * D];
__device__ float g_v     [S * NKV * D];
__device__ float g_ctx   [S * NH * D];
__device__ float g_hid2  [S * H];
__device__ float g_hnorm [S * H];
__device__ int   g_topk_id[NA];
__device__ float g_topk_w [NA];
__device__ int   g_cnt   [E];
__device__ int   g_off   [E + 1];
__device__ int   g_cur   [E];
__device__ int   g_tok   [NA];     // expert-grouped token index
__device__ float g_ew    [NA];     // expert-grouped combine weight
__device__ int   g_pos   [NA];     // assignment a -> expert-grouped row
__device__ float g_act   [NA * IM];        // grouped weighted SwiGLU activations
__device__ float g_part  [(size_t)NA * H]; // grouped down-proj rows

__device__ __forceinline__ float* bufptr(int b) {
    switch (b) {
        case 0: return g_xnorm;
        case 4: return g_ctx;
        case 5: return g_hid2;
        case 6: return g_hnorm;
    }
    return nullptr;
}

// ---------------- helpers ----------------
__device__ __forceinline__ unsigned smaddr(const void* p) {
    return (unsigned)__cvta_generic_to_shared(p);
}
__device__ __forceinline__ unsigned cvt_tf32(float f) {
    unsigned u; asm("cvt.rna.tf32.f32 %0, %1;" : "=r"(u) : "f"(f)); return u;
}
__device__ __forceinline__ void cpa16(unsigned s, const void* g) {
    asm volatile("cp.async.ca.shared.global [%0], [%1], 16;" :: "r"(s), "l"(g));
}
__device__ __forceinline__ void cp_commit() {
    asm volatile("cp.async.commit_group;");
}
__device__ __forceinline__ void cp_wait1() {
    asm volatile("cp.async.wait_group 1;");
}
__device__ __forceinline__ void cp_wait0() {
    asm volatile("cp.async.wait_group 0;");
}
__device__ __forceinline__ void mma_tf32(float c[4], const unsigned a[4], const unsigned b[2]) {
    asm volatile(
        "mma.sync.aligned.m16n8k8.row.col.f32.tf32.tf32.f32 "
        "{%0,%1,%2,%3}, {%4,%5,%6,%7}, {%8,%9}, {%0,%1,%2,%3};\n"
        : "+f"(c[0]), "+f"(c[1]), "+f"(c[2]), "+f"(c[3])
        : "r"(a[0]), "r"(a[1]), "r"(a[2]), "r"(a[3]), "r"(b[0]), "r"(b[1]));
}

// ---------------- RMSNorm ----------------
__global__ void rmsnorm_k(const float* __restrict__ x_ext, int xBuf,
                          const float* __restrict__ g, int outBuf) {
    const float* x = x_ext ? x_ext : bufptr(xBuf);
    float* out = bufptr(outBuf);
    int row = blockIdx.x, tid = threadIdx.x;
    const float* xr = x + (size_t)row * H;
    float ss = 0.f;
    for (int j = tid; j < H; j += 256) { float v = xr[j]; ss += v * v; }
    for (int o = 16; o; o >>= 1) ss += __shfl_xor_sync(0xffffffffu, ss, o);
    __shared__ float red[8];
    if ((tid & 31) == 0) red[tid >> 5] = ss;
    __syncthreads();
    if (tid < 32) {
        float v = (tid < 8) ? red[tid] : 0.f;
        for (int o = 4; o; o >>= 1) v += __shfl_xor_sync(0xffffffffu, v, o);
        if (tid == 0) red[0] = v;
    }
    __syncthreads();
    float inv = rsqrtf(red[0] / (float)H + EPS);
    for (int j = tid; j < H; j += 256) out[(size_t)row * H + j] = xr[j] * inv * g[j];
}

// ---------------- dense TF32 GEMM, cp.async double-buffered ----------------
// CTA tile 128x64, 8 warps (4m x 2n). mode 0: fused QKV (N=3072), mode 1: Wo.
__global__ __launch_bounds__(256) void dense_tf32(int aBuf,
        const float* __restrict__ W0, const float* __restrict__ W1,
        const float* __restrict__ W2, const float* __restrict__ res,
        int mode, int K) {
    const float* A = bufptr(aBuf);
    int m0 = blockIdx.y * 128;
    int n0c = blockIdx.x * 64;
    const float* B; int ldb, nb; float* Cp; int ldo;
    if (mode == 0) {
        if (n0c < 2048)      { B = W0; ldb = 2048; nb = n0c;        Cp = g_q; ldo = 2048; }
        else if (n0c < 2560) { B = W1; ldb = 512;  nb = n0c - 2048; Cp = g_k; ldo = 512; }
        else                 { B = W2; ldb = 512;  nb = n0c - 2560; Cp = g_v; ldo = 512; }
    } else { B = W0; ldb = 2048; nb = n0c; Cp = g_hid2; ldo = 2048; }
    __shared__ __align__(16) float As[2][128 * AST];
    __shared__ __align__(16) float Bs[2][KC * BST];
    int tid = threadIdx.x, lane = tid & 31, wid = tid >> 5;
    int wm = wid >> 1, wn = wid & 1;

    auto load_chunk = [&](int k0, int buf) {
        #pragma unroll
        for (int i = 0; i < 2; i++) {
            int id = tid + i * 256;
            int row = id >> 2, q = (id & 3) * 4;
            cpa16(smaddr(&As[buf][row * AST + q]),
                  A + (size_t)(m0 + row) * K + k0 + q);
        }
        int kr = tid >> 4, nq = (tid & 15) * 4;
        cpa16(smaddr(&Bs[buf][kr * BST + nq]),
              B + (size_t)(k0 + kr) * ldb + nb + nq);
        cp_commit();
    };

    float acc[2][4][4] = {};
    int NCH = K / KC;
    load_chunk(0, 0);
    for (int c = 0; c < NCH; c++) {
        int buf = c & 1;
        if (c + 1 < NCH) { load_chunk((c + 1) * KC, buf ^ 1); cp_wait1(); }
        else             { cp_wait0(); }
        __syncthreads();
        #pragma unroll
        for (int ks = 0; ks < 2; ks++) {
            int kk = ks * 8;
            unsigned Af[2][4];
            #pragma unroll
            for (int m = 0; m < 2; m++) {
                const float* ap = &As[buf][(wm * 32 + m * 16 + (lane >> 2)) * AST + kk + (lane & 3)];
                Af[m][0] = cvt_tf32(ap[0]);
                Af[m][1] = cvt_tf32(ap[8 * AST]);
                Af[m][2] = cvt_tf32(ap[4]);
                Af[m][3] = cvt_tf32(ap[8 * AST + 4]);
            }
            #pragma unroll
            for (int nt = 0; nt < 4; nt++) {
                const float* bp = &Bs[buf][(kk + (lane & 3)) * BST + wn * 32 + nt * 8 + (lane >> 2)];
                unsigned Bf[2] = { cvt_tf32(bp[0]), cvt_tf32(bp[4 * BST]) };
                #pragma unroll
                for (int m = 0; m < 2; m++) mma_tf32(acc[m][nt], Af[m], Bf);
            }
        }
        __syncthreads();
    }
    #pragma unroll
    for (int m = 0; m < 2; m++)
        #pragma unroll
        for (int nt = 0; nt < 4; nt++)
            #pragma unroll
            for (int r = 0; r < 4; r++) {
                int row = m0 + wm * 32 + m * 16 + (lane >> 2) + ((r >= 2) ? 8 : 0);
                int col = wn * 32 + nt * 8 + (lane & 3) * 2 + (r & 1);
                size_t oidx = (size_t)row * ldo + nb + col;
                float v = acc[m][nt][r];
                if (res) v += res[oidx];   // mode 1: ldo=2048, nb=n0c -> same index
                Cp[oidx] = v;
            }
}

// ---------------- causal flash attention (fp32) ----------------
__global__ __launch_bounds__(256) void attn_k() {
    constexpr int KT = 32;
    constexpr float SC = 0.0883883476483184f; // 1/sqrt(128)
    int qt = blockIdx.x, h = blockIdx.y;
    int kvh = h / (NH / NKV);
    int tid = threadIdx.x;
    int qi = tid >> 2, qr = tid & 3;
    int qrow = qt * 64 + qi;
    int d0 = qr * 32;
    __shared__ float Ks[KT][D];
    __shared__ float Vs[KT][D];
    float qreg[32], acc[32];
    #pragma unroll
    for (int d = 0; d < 32; d++) {
        qreg[d] = g_q[(size_t)qrow * (NH * D) + h * D + d0 + d] * SC;
        acc[d] = 0.f;
    }
    float m = -1e30f, l = 0.f;
    int ktiles = qt * 2 + 2;
    for (int kt = 0; kt < ktiles; kt++) {
        int kb = kt * KT;
        for (int idx = tid; idx < KT * D; idx += 256) {
            int r = idx >> 7, c = idx & 127;
            Ks[r][c] = g_k[(size_t)(kb + r) * (NKV * D) + kvh * D + c];
            Vs[r][c] = g_v[(size_t)(kb + r) * (NKV * D) + kvh * D + c];
        }
        __syncthreads();
        float sc[KT];
        #pragma unroll
        for (int j = 0; j < KT; j++) {
            float p = 0.f;
            #pragma unroll
            for (int d = 0; d < 32; d++) p += qreg[d] * Ks[j][d0 + d];
            p += __shfl_xor_sync(0xffffffffu, p, 1);
            p += __shfl_xor_sync(0xffffffffu, p, 2);
            sc[j] = (kb + j <= qrow) ? p : -1e30f;
        }
        float tm = m;
        #pragma unroll
        for (int j = 0; j < KT; j++) tm = fmaxf(tm, sc[j]);
        float corr = __expf(m - tm);
        m = tm;
        l *= corr;
        #pragma unroll
        for (int d = 0; d < 32; d++) acc[d] *= corr;
        #pragma unroll
        for (int j = 0; j < KT; j++) {
            float p = __expf(sc[j] - m);
            l += p;
            #pragma unroll
            for (int d = 0; d < 32; d++) acc[d] += p * Vs[j][d0 + d];
        }
        __syncthreads();
    }
    float inv = 1.f / l;
    #pragma unroll
    for (int d = 0; d < 32; d++)
        g_ctx[(size_t)qrow * (NH * D) + h * D + d0 + d] = acc[d] * inv;
}

// ---------------- router: logits, softmax-top8, counts ----------------
__global__ void zero_cnt_k() { if (threadIdx.x < E) g_cnt[threadIdx.x] = 0; }

__global__ void router_k(const float* __restrict__ Wg) {
    int t = blockIdx.x, tid = threadIdx.x;   // blockDim = 64
    __shared__ float sh[H];
    __shared__ float lg[E];
    for (int j = tid; j < H; j += 64) sh[j] = g_hnorm[(size_t)t * H + j];
    __syncthreads();
    float lo = 0.f;
    for (int j = 0; j < H; j++) lo += sh[j] * Wg[(size_t)j * E + tid];
    lg[tid] = lo;
    __syncthreads();
    if (tid == 0) {
        float tmp[E];
        for (int e = 0; e < E; e++) tmp[e] = lg[e];
        int   id[TK]; float w[TK];
        for (int k = 0; k < TK; k++) {
            int best = 0; float bv = tmp[0];
            for (int e = 1; e < E; e++) if (tmp[e] > bv) { bv = tmp[e]; best = e; }
            id[k] = best; w[k] = bv; tmp[best] = -1e30f;
        }
        float mx = w[0], s = 0.f;
        for (int k = 0; k < TK; k++) { w[k] = expf(w[k] - mx); s += w[k]; }
        float inv = 1.f / s;
        for (int k = 0; k < TK; k++) {
            g_topk_id[t * TK + k] = id[k];
            g_topk_w [t * TK + k] = w[k] * inv;
            atomicAdd(&g_cnt[id[k]], 1);
        }
    }
}

__global__ void offsets_k() {
    if (threadIdx.x == 0) {
        int run = 0;
        for (int e = 0; e < E; e++) { g_off[e] = run; g_cur[e] = run; run += g_cnt[e]; }
        g_off[E] = run;
    }
}

__global__ void scatter_k() {
    int a = blockIdx.x * blockDim.x + threadIdx.x;
    if (a < NA) {
        int e = g_topk_id[a];
        int pos = atomicAdd(&g_cur[e], 1);
        g_tok[pos] = a >> 3;
        g_ew [pos] = g_topk_w[a];
        g_pos[a]   = pos;
    }
}

// ---------------- MoE gate/up TF32 GEMM + SwiGLU, pipelined ----------------
// grid (IM/64, 8, E), block 256. CTA tile 128 x 64, K = H.
__global__ __launch_bounds__(256) void moe_gateup_tf32(const float* __restrict__ Wgate,
                                                       const float* __restrict__ Wup) {
    int e = blockIdx.z;
    int base = g_off[e], cnt = g_off[e + 1] - base;
    int t0 = blockIdx.y * 128;
    if (t0 >= cnt) return;
    int i0 = blockIdx.x * 64;
    __shared__ __align__(16) float As[2][128 * AST];
    __shared__ __align__(16) float Bg[2][KC * BST];
    __shared__ __align__(16) float Bu[2][KC * BST];
    __shared__ int   stok[128];
    __shared__ float swt[128];
    int tid = threadIdx.x, lane = tid & 31, wid = tid >> 5;
    int wm = wid >> 1, wn = wid & 1;
    if (tid < 128) {
        int r = t0 + tid;
        if (r < cnt) { stok[tid] = g_tok[base + r]; swt[tid] = g_ew[base + r]; }
        else         { stok[tid] = 0; swt[tid] = 0.f; }
    }
    __syncthreads();
    const float* WgE = Wgate + (size_t)e * H * IM;
    const float* WuE = Wup   + (size_t)e * H * IM;

    auto load_chunk = [&](int k0, int buf) {
        #pragma unroll
        for (int i = 0; i < 2; i++) {
            int id = tid + i * 256;
            int row = id >> 2, q = (id & 3) * 4;
            cpa16(smaddr(&As[buf][row * AST + q]),
                  g_hnorm + (size_t)stok[row] * H + k0 + q);
        }
        int kr = tid >> 4, nq = (tid & 15) * 4;
        cpa16(smaddr(&Bg[buf][kr * BST + nq]),
              WgE + (size_t)(k0 + kr) * IM + i0 + nq);
        cpa16(smaddr(&Bu[buf][kr * BST + nq]),
              WuE + (size_t)(k0 + kr) * IM + i0 + nq);
        cp_commit();
    };

    float accg[2][4][4] = {};
    float accu[2][4][4] = {};
    constexpr int NCH = H / KC;
    load_chunk(0, 0);
    for (int c = 0; c < NCH; c++) {
        int buf = c & 1;
        if (c + 1 < NCH) { load_chunk((c + 1) * KC, buf ^ 1); cp_wait1(); }
        else             { cp_wait0(); }
        __syncthreads();
        #pragma unroll
        for (int ks = 0; ks < 2; ks++) {
            int kk = ks * 8;
            unsigned Af[2][4];
            #pragma unroll
            for (int m = 0; m < 2; m++) {
                const float* ap = &As[buf][(wm * 32 + m * 16 + (lane >> 2)) * AST + kk + (lane & 3)];
                Af[m][0] = cvt_tf32(ap[0]);
                Af[m][1] = cvt_tf32(ap[8 * AST]);
                Af[m][2] = cvt_tf32(ap[4]);
                Af[m][3] = cvt_tf32(ap[8 * AST + 4]);
            }
            #pragma unroll
            for (int nt = 0; nt < 4; nt++) {
                int off = (kk + (lane & 3)) * BST + wn * 32 + nt * 8 + (lane >> 2);
                unsigned Gf[2] = { cvt_tf32(Bg[buf][off]), cvt_tf32(Bg[buf][off + 4 * BST]) };
                unsigned Uf[2] = { cvt_tf32(Bu[buf][off]), cvt_tf32(Bu[buf][off + 4 * BST]) };
                #pragma unroll
                for (int m = 0; m < 2; m++) {
                    mma_tf32(accg[m][nt], Af[m], Gf);
                    mma_tf32(accu[m][nt], Af[m], Uf);
                }
            }
        }
        __syncthreads();
    }
    #pragma unroll
    for (int m = 0; m < 2; m++)
        #pragma unroll
        for (int nt = 0; nt < 4; nt++)
            #pragma unroll
            for (int r = 0; r < 4; r++) {
                int row = wm * 32 + m * 16 + (lane >> 2) + ((r >= 2) ? 8 : 0);
                int col = wn * 32 + nt * 8 + (lane & 3) * 2 + (r & 1);
                int gr = t0 + row;
                if (gr < cnt) {
                    float gg = accg[m][nt][r], uu = accu[m][nt][r];
                    float a = (gg / (1.f + __expf(-gg))) * uu * swt[row];
                    g_act[(size_t)(base + gr) * IM + i0 + col] = a;
                }
            }
}

// ---------------- MoE down TF32 GEMM -> grouped partial rows, pipelined ----
// grid (H/64, 8, E), block 256. CTA tile 128 x 64, K = IM.
__global__ __launch_bounds__(256) void moe_down_tf32(const float* __restrict__ Wdown) {
    int e = blockIdx.z;
    int base = g_off[e], cnt = g_off[e + 1] - base;
    int t0 = blockIdx.y * 128;
    if (t0 >= cnt) return;
    int h0 = blockIdx.x * 64;
    __shared__ __align__(16) float As[2][128 * AST];
    __shared__ __align__(16) float Bs[2][KC * BST];
    int tid = threadIdx.x, lane = tid & 31, wid = tid >> 5;
    int wm = wid >> 1, wn = wid & 1;
    const float* WdE = Wdown + (size_t)e * IM * H;

    auto load_chunk = [&](int k0, int buf) {
        #pragma unroll
        for (int i = 0; i < 2; i++) {
            int id = tid + i * 256;
            int row = id >> 2, q = (id & 3) * 4;
            int gr = t0 + row; if (gr >= cnt) gr = cnt - 1;
            cpa16(smaddr(&As[buf][row * AST + q]),
                  g_act + (size_t)(base + gr) * IM + k0 + q);
        }
        int kr = tid >> 4, nq = (tid & 15) * 4;
        cpa16(smaddr(&Bs[buf][kr * BST + nq]),
              WdE + (size_t)(k0 + kr) * H + h0 + nq);
        cp_commit();
    };

    float acc[2][4][4] = {};
    constexpr int NCH = IM / KC;
    load_chunk(0, 0);
    for (int c = 0; c < NCH; c++) {
        int buf = c & 1;
        if (c + 1 < NCH) { load_chunk((c + 1) * KC, buf ^ 1); cp_wait1(); }
        else             { cp_wait0(); }
        __syncthreads();
        #pragma unroll
        for (int ks = 0; ks < 2; ks++) {
            int kk = ks * 8;
            unsigned Af[2][4];
            #pragma unroll
            for (int m = 0; m < 2; m++) {
                const float* ap = &As[buf][(wm * 32 + m * 16 + (lane >> 2)) * AST + kk + (lane & 3)];
                Af[m][0] = cvt_tf32(ap[0]);
                Af[m][1] = cvt_tf32(ap[8 * AST]);
                Af[m][2] = cvt_tf32(ap[4]);
                Af[m][3] = cvt_tf32(ap[8 * AST + 4]);
            }
            #pragma unroll
            for (int nt = 0; nt < 4; nt++) {
                int off = (kk + (lane & 3)) * BST + wn * 32 + nt * 8 + (lane >> 2);
                unsigned Bf[2] = { cvt_tf32(Bs[buf][off]), cvt_tf32(Bs[buf][off + 4 * BST]) };
                #pragma unroll
                for (int m = 0; m < 2; m++) mma_tf32(acc[m][nt], Af[m], Bf);
            }
        }
        __syncthreads();
    }
    #pragma unroll
    for (int m = 0; m < 2; m++)
        #pragma unroll
        for (int nt = 0; nt < 4; nt++)
            #pragma unroll
            for (int r = 0; r < 4; r++) {
                int row = wm * 32 + m * 16 + (lane >> 2) + ((r >= 2) ? 8 : 0);
                int col = wn * 32 + nt * 8 + (lane & 3) * 2 + (r & 1);
                int gr = t0 + row;
                if (gr < cnt)
                    g_part[(size_t)(base + gr) * H + h0 + col] = acc[m][nt][r];
            }
}

// ---------------- finalize: residual + sum of 8 grouped partial rows -------
__global__ void finalize_k(float* __restrict__ out) {
    size_t idx = (size_t)blockIdx.x * 256 + threadIdx.x;   // S*H total
    int t = (int)(idx >> 11);
    int hc = (int)(idx & 2047);
    float v = g_hid2[idx];
    #pragma unroll
    for (int k = 0; k < TK; k++)
        v += g_part[(size_t)g_pos[t * TK + k] * H + hc];
    out[idx] = v;
}

// ---------------- launch ----------------
extern "C" void kernel_launch(void* const* d_in, const int* in_sizes, int n_in,
                              void* d_out, int out_size) {
    const float* hidden = (const float*)d_in[0];
    const float* ln1_g  = (const float*)d_in[1];
    const float* ln2_g  = (const float*)d_in[2];
    const float* Wq     = (const float*)d_in[3];
    const float* Wk     = (const float*)d_in[4];
    const float* Wv     = (const float*)d_in[5];
    const float* Wo     = (const float*)d_in[6];
    const float* Wg     = (const float*)d_in[7];
    const float* Wgate  = (const float*)d_in[8];
    const float* Wup    = (const float*)d_in[9];
    const float* Wdown  = (const float*)d_in[10];
    float* out = (float*)d_out;

    // 1. input RMSNorm -> buf0 (xnorm)
    rmsnorm_k<<<S, 256>>>(hidden, -1, ln1_g, 0);
    // 2. fused QKV projection (TF32 MMA, cp.async pipelined)
    dense_tf32<<<dim3(48, S / 128), 256>>>(0, Wq, Wk, Wv, nullptr, 0, H);
    // 3. causal GQA attention -> ctx(4)
    attn_k<<<dim3(S / 64, NH), 256>>>();
    // 4. output projection + residual -> hid2(5)
    dense_tf32<<<dim3(32, S / 128), 256>>>(4, Wo, nullptr, nullptr, hidden, 1, NH * D);
    // 5. post-attn RMSNorm -> hnorm(6)
    rmsnorm_k<<<S, 256>>>(nullptr, 5, ln2_g, 6);
    // 6. router + dispatch
    zero_cnt_k<<<1, 64>>>();
    router_k<<<S, 64>>>(Wg);
    offsets_k<<<1, 1>>>();
    scatter_k<<<(NA + 255) / 256, 256>>>();
    // 7. expert gate/up + SwiGLU
    moe_gateup_tf32<<<dim3(IM / 64, 8, E), 256>>>(Wgate, Wup);
    // 8. expert down-proj
    moe_down_tf32<<<dim3(H / 64, 8, E), 256>>>(Wdown);
    // 9. residual + combine
    finalize_k<<<(S * H) / 256, 256>>>(out);
    (void)in_sizes; (void)n_in; (void)out_size;
}